// round 6
// baseline (speedup 1.0000x reference)
#include <cuda_runtime.h>
#include <cstdint>

// LinearBlendSkinning, R6: persistent blocks + cp.async double-buffered pipeline.
// out[n] = (sum_j w[n,j]*SE3[j])[:3,:3] @ p[n] + (...)[:3,3], N=1e6, J=55.
//
// R5 finding: load-phase and compute-phase serialize (DRAM 45%, fma 27%,
// nothing saturated). Fix: each block processes ~17 tiles, prefetching the
// next tile's weights+points via cp.async into the alternate SMEM buffer
// while computing the current one. SE3 staged to SMEM once per block
// (no per-replay constant-copy node).

#define NJ   55
#define BT   128
#define BV   128
#define W_TILE (BV * NJ)   // 7040 floats = 28160 B
#define P_TILE (BV * 3)    // 384 floats = 1536 B
#define GRID_PERSIST 456   // 152 SMs * 3 blocks

#define FMA2(acc, s, m) \
    asm("fma.rn.f32x2 %0, %1, %2, %0;" : "+l"(acc) : "l"(s), "l"(m))
#define PACK_DUP(dst, f) \
    asm("mov.b64 %0, {%1, %1};" : "=l"(dst) : "f"(f))
#define UNPACK2(lo, hi, src) \
    asm("mov.b64 {%0, %1}, %2;" : "=f"(lo), "=f"(hi) : "l"(src))

#define CP16(dst_u32, src_ptr) \
    asm volatile("cp.async.cg.shared.global [%0], [%1], 16;" :: "r"(dst_u32), "l"(src_ptr))
#define CP4(dst_u32, src_ptr) \
    asm volatile("cp.async.ca.shared.global [%0], [%1], 4;"  :: "r"(dst_u32), "l"(src_ptr))
#define CP_COMMIT() asm volatile("cp.async.commit_group;" ::: "memory")
#define CP_WAIT(n)  asm volatile("cp.async.wait_group %0;" :: "n"(n) : "memory")

__device__ __forceinline__ uint32_t smem_u32(const void* p) {
    return (uint32_t)__cvta_generic_to_shared(p);
}

// dynamic SMEM layout: w[2][W_TILE] | p[2][P_TILE] | se3[NJ*3] (16B aligned)
#define SMEM_BYTES ((2 * W_TILE + 2 * P_TILE) * 4 + NJ * 3 * 16)

__global__ void __launch_bounds__(BT) lbs_kernel(
    const float* __restrict__ points,   // [N,3]
    const float* __restrict__ weights,  // [N,55]
    const float* __restrict__ se3g,     // [55,4,4]
    float* __restrict__ out,            // [N,3]
    int N, int nt)
{
    extern __shared__ unsigned char smem_raw[];
    float* w_s = (float*)smem_raw;                                   // [2][W_TILE]
    float* p_s = (float*)(smem_raw + 2 * W_TILE * 4);                // [2][P_TILE]
    ulonglong2* se3_s = (ulonglong2*)(smem_raw + (2 * W_TILE + 2 * P_TILE) * 4);

    const int tid = threadIdx.x;

    // ---- SE3 rows 0..2 -> SMEM, once per persistent block ----
    for (int idx = tid; idx < NJ * 3; idx += BT) {
        const int j = idx / 3, k = idx - j * 3;
        se3_s[idx] = *reinterpret_cast<const ulonglong2*>(se3g + j * 16 + k * 4);
    }

    const int stride = gridDim.x;
    int t   = blockIdx.x;
    int buf = 0;

    // ---- stage one tile asynchronously ----
    auto stage = [&](int b, int tt) {
        const int nv = min(BV, N - tt * BV);
        const uint32_t wdst = smem_u32(w_s + b * W_TILE);
        const uint32_t pdst = smem_u32(p_s + b * P_TILE);
        const float* __restrict__ wsrc = weights + (size_t)tt * W_TILE;
        const float* __restrict__ psrc = points  + (size_t)tt * P_TILE;
        if (nv == BV) {
            #pragma unroll 4
            for (int i = tid; i < W_TILE / 4; i += BT)
                CP16(wdst + i * 16, wsrc + i * 4);
            if (tid < P_TILE / 4)
                CP16(pdst + tid * 16, psrc + tid * 4);
        } else {  // last partial tile only
            const int nw = nv * NJ;
            for (int i = tid; i < nw; i += BT) CP4(wdst + i * 4, wsrc + i);
            const int np = nv * 3;
            for (int i = tid; i < np; i += BT) CP4(pdst + i * 4, psrc + i);
        }
    };

    if (t < nt) stage(0, t);
    CP_COMMIT();

    for (; t < nt; t += stride) {
        const int  tn = t + stride;
        const bool pf = (tn < nt);

        __syncthreads();                 // prior compute done reading buf^1
        if (pf) stage(buf ^ 1, tn);
        CP_COMMIT();
        if (pf) { CP_WAIT(1); } else { CP_WAIT(0); }   // tile t landed
        __syncthreads();                 // visible to all threads

        // ---- compute tile t from buffer `buf` ----
        const int nv = min(BV, N - t * BV);
        const float* __restrict__ wp = w_s + buf * W_TILE + tid * NJ;
        const float* __restrict__ pp = p_s + buf * P_TILE + tid * 3;
        const float px = pp[0], py = pp[1], pz = pp[2];

        unsigned long long a00 = 0, a01 = 0, a10 = 0, a11 = 0, a20 = 0, a21 = 0;

        #pragma unroll 11
        for (int j = 0; j < NJ; j++) {
            const float w = wp[j];
            unsigned long long ww;
            PACK_DUP(ww, w);
            const ulonglong2 r0 = se3_s[j * 3 + 0];
            const ulonglong2 r1 = se3_s[j * 3 + 1];
            const ulonglong2 r2 = se3_s[j * 3 + 2];
            FMA2(a00, ww, r0.x); FMA2(a01, ww, r0.y);
            FMA2(a10, ww, r1.x); FMA2(a11, ww, r1.y);
            FMA2(a20, ww, r2.x); FMA2(a21, ww, r2.y);
        }

        if (tid < nv) {
            const int v = t * BV + tid;
            float m0, m1, m2, m3, o0, o1, o2;
            UNPACK2(m0, m1, a00); UNPACK2(m2, m3, a01);
            o0 = fmaf(m0, px, fmaf(m1, py, fmaf(m2, pz, m3)));
            UNPACK2(m0, m1, a10); UNPACK2(m2, m3, a11);
            o1 = fmaf(m0, px, fmaf(m1, py, fmaf(m2, pz, m3)));
            UNPACK2(m0, m1, a20); UNPACK2(m2, m3, a21);
            o2 = fmaf(m0, px, fmaf(m1, py, fmaf(m2, pz, m3)));
            out[3 * v + 0] = o0;
            out[3 * v + 1] = o1;
            out[3 * v + 2] = o2;
        }
        buf ^= 1;
    }
}

extern "C" void kernel_launch(void* const* d_in, const int* in_sizes, int n_in,
                              void* d_out, int out_size)
{
    const float* points  = (const float*)d_in[0];  // [N,3]
    const float* weights = (const float*)d_in[1];  // [N,55]
    const float* se3     = (const float*)d_in[2];  // [55,4,4]
    float* out           = (float*)d_out;          // [N,3]

    const int N  = in_sizes[0] / 3;
    const int nt = (N + BV - 1) / BV;
    const int grid = nt < GRID_PERSIST ? nt : GRID_PERSIST;

    static bool attr_set = false;
    if (!attr_set) {
        cudaFuncSetAttribute(lbs_kernel,
                             cudaFuncAttributeMaxDynamicSharedMemorySize,
                             SMEM_BYTES);
        attr_set = true;
    }
    lbs_kernel<<<grid, BT, SMEM_BYTES>>>(points, weights, se3, out, N, nt);
}

// round 7
// speedup vs baseline: 1.2659x; 1.2659x over previous
#include <cuda_runtime.h>
#include <cstdint>

// LinearBlendSkinning, R7: warp-autonomous tiles, no block barriers.
// out[n] = (sum_j w[n,j]*SE3[j])[:3,:3] @ p[n] + (...)[:3,3], N=1e6, J=55.
//
// Findings driving this version:
//  - R5 (const mem): LDC has an 8-cyc/SMSP structural floor -> 330 LDC/vertex
//    = ~70us chip-wide. SE3 must live in SMEM (LDS.128 broadcast ~1cyc).
//  - R4/R6: __syncthreads keeps all warps of a block in lockstep ->
//    load phases and compute phases serialize SM-wide -> DRAM stuck ~45%.
// Fix: each WARP stages its own 32 contiguous weight rows (7040B, coalesced,
// 14 front-batched LDG.128 = MLP 14) into its private SMEM slice, __syncwarp,
// computes, repeats (persistent grid-stride). Warps free-run and desync, so
// staging warps keep HBM saturated while others compute.

#define NJ     55
#define WARPS  8
#define BT     (WARPS * 32)        // 256
#define WSLICE (32 * NJ)           // 1760 floats = 7040 B per warp slice
#define NCHUNK 14                  // ceil(1760/4/32) float4 loads per lane

#define FMA2(acc, s, m) \
    asm("fma.rn.f32x2 %0, %1, %2, %0;" : "+l"(acc) : "l"(s), "l"(m))
#define PACK_DUP(dst, f) \
    asm("mov.b64 %0, {%1, %1};" : "=l"(dst) : "f"(f))
#define UNPACK2(lo, hi, src) \
    asm("mov.b64 {%0, %1}, %2;" : "=f"(lo), "=f"(hi) : "l"(src))

// dynamic SMEM: se3 rows (16B each) then per-warp weight slices
#define SMEM_BYTES (NJ * 3 * 16 + WARPS * WSLICE * 4)

__global__ void __launch_bounds__(BT, 3) lbs_kernel(
    const float* __restrict__ points,   // [N,3]
    const float* __restrict__ weights,  // [N,55]
    const float* __restrict__ se3g,     // [55,4,4]
    float* __restrict__ out,            // [N,3]
    int N, int ntiles)
{
    extern __shared__ unsigned char smem_raw[];
    ulonglong2* se3_s = (ulonglong2*)smem_raw;                  // [NJ*3]
    float*      w_all = (float*)(smem_raw + NJ * 3 * 16);       // [WARPS][WSLICE]

    const int tid  = threadIdx.x;
    const int wid  = tid >> 5;
    const int lane = tid & 31;

    // ---- SE3 rows 0..2 -> SMEM once per persistent block ----
    for (int idx = tid; idx < NJ * 3; idx += BT) {
        const int j = idx / 3, k = idx - j * 3;
        se3_s[idx] = *reinterpret_cast<const ulonglong2*>(se3g + j * 16 + k * 4);
    }
    __syncthreads();   // only block-wide sync in the kernel

    float* __restrict__ ws = w_all + wid * WSLICE;
    const int tstride = gridDim.x * WARPS;

    for (int t = blockIdx.x * WARPS + wid; t < ntiles; t += tstride) {
        const int base = t * 32;
        const int nv   = min(32, N - base);
        const int v    = base + lane;
        const bool valid = (lane < nv);
        const int pv   = valid ? v : base;

        // Issue point loads early (independent of staging).
        const float px = points[3 * pv + 0];
        const float py = points[3 * pv + 1];
        const float pz = points[3 * pv + 2];

        // ---- stage this warp's 32 weight rows: contiguous, coalesced ----
        if (nv == 32) {
            const float4* __restrict__ src =
                reinterpret_cast<const float4*>(weights + (size_t)base * NJ);
            float4* __restrict__ dst = reinterpret_cast<float4*>(ws);
            float4 r[NCHUNK];
            #pragma unroll
            for (int k = 0; k < NCHUNK; k++) {           // front-batched LDGs
                const int i = lane + k * 32;
                if (i < WSLICE / 4) r[k] = src[i];
            }
            #pragma unroll
            for (int k = 0; k < NCHUNK; k++) {
                const int i = lane + k * 32;
                if (i < WSLICE / 4) dst[i] = r[k];
            }
        } else {
            const float* __restrict__ src = weights + (size_t)base * NJ;
            for (int i = lane; i < nv * NJ; i += 32) ws[i] = src[i];
        }
        __syncwarp();

        // ---- compute: lane owns vertex base+lane ----
        unsigned long long a00 = 0, a01 = 0, a10 = 0, a11 = 0, a20 = 0, a21 = 0;
        const float* __restrict__ wp = ws + lane * NJ;   // word-stride 55: conflict-free

        #pragma unroll 11
        for (int j = 0; j < NJ; j++) {
            const float w = wp[j];
            unsigned long long ww;
            PACK_DUP(ww, w);
            const ulonglong2 r0 = se3_s[j * 3 + 0];      // LDS.128 broadcast
            const ulonglong2 r1 = se3_s[j * 3 + 1];
            const ulonglong2 r2 = se3_s[j * 3 + 2];
            FMA2(a00, ww, r0.x); FMA2(a01, ww, r0.y);
            FMA2(a10, ww, r1.x); FMA2(a11, ww, r1.y);
            FMA2(a20, ww, r2.x); FMA2(a21, ww, r2.y);
        }

        if (valid) {
            float m0, m1, m2, m3, o0, o1, o2;
            UNPACK2(m0, m1, a00); UNPACK2(m2, m3, a01);
            o0 = fmaf(m0, px, fmaf(m1, py, fmaf(m2, pz, m3)));
            UNPACK2(m0, m1, a10); UNPACK2(m2, m3, a11);
            o1 = fmaf(m0, px, fmaf(m1, py, fmaf(m2, pz, m3)));
            UNPACK2(m0, m1, a20); UNPACK2(m2, m3, a21);
            o2 = fmaf(m0, px, fmaf(m1, py, fmaf(m2, pz, m3)));
            out[3 * v + 0] = o0;
            out[3 * v + 1] = o1;
            out[3 * v + 2] = o2;
        }
        __syncwarp();   // done reading slice before next stage overwrites
    }
}

extern "C" void kernel_launch(void* const* d_in, const int* in_sizes, int n_in,
                              void* d_out, int out_size)
{
    const float* points  = (const float*)d_in[0];  // [N,3]
    const float* weights = (const float*)d_in[1];  // [N,55]
    const float* se3     = (const float*)d_in[2];  // [55,4,4]
    float* out           = (float*)d_out;          // [N,3]

    const int N      = in_sizes[0] / 3;
    const int ntiles = (N + 31) / 32;

    int grid = 148 * 3;                       // persistent: 3 blocks/SM target
    const int maxg = (ntiles + WARPS - 1) / WARPS;
    if (grid > maxg) grid = maxg;

    static bool attr_set = false;
    if (!attr_set) {
        cudaFuncSetAttribute(lbs_kernel,
                             cudaFuncAttributeMaxDynamicSharedMemorySize,
                             SMEM_BYTES);
        attr_set = true;
    }
    lbs_kernel<<<grid, BT, SMEM_BYTES>>>(points, weights, se3, out, N, ntiles);
}

// round 11
// speedup vs baseline: 1.5612x; 1.2333x over previous
#include <cuda_runtime.h>
#include <cstdint>

// LinearBlendSkinning, R8: warp-autonomous tiles + VPT=2 to amortize SE3 LDS.
// out[n] = (sum_j w[n,j]*SE3[j])[:3,:3] @ p[n] + (...)[:3,3], N=1e6, J=55.
//
// R7 finding: L1/LSU wavefront throughput is the binding resource (L1=78%);
// the dominant term is 165 SE3 LDS.128 broadcasts per 32-vertex tile
// (5.2 wf/vertex). Fix: each thread computes TWO vertices (l and l+32 of a
// 64-vertex warp tile) so each SE3 row load feeds 12 FFMA2 instead of 6.
// The (l, l+32) split keeps both weight LDS streams at odd word-stride 55
// (conflict-free); an adjacent 2l/2l+1 split would give even stride = 2-way
// bank conflicts. No block barriers (R4/R6 lesson): warps free-run.

#define NJ     55
#define WARPS  4
#define BT     (WARPS * 32)        // 128
#define TV     64                  // vertices per warp tile
#define WSLICE (TV * NJ)           // 3520 floats = 14080 B per warp slice
#define NQ     (WSLICE / 4)        // 880 float4
#define NCHUNK 28                  // ceil(880/32)

#define FMA2(acc, s, m) \
    asm("fma.rn.f32x2 %0, %1, %2, %0;" : "+l"(acc) : "l"(s), "l"(m))
#define PACK_DUP(dst, f) \
    asm("mov.b64 %0, {%1, %1};" : "=l"(dst) : "f"(f))
#define UNPACK2(lo, hi, src) \
    asm("mov.b64 {%0, %1}, %2;" : "=f"(lo), "=f"(hi) : "l"(src))

// dynamic SMEM: se3 rows (16B each) then per-warp weight slices
#define SMEM_BYTES (NJ * 3 * 16 + WARPS * WSLICE * 4)

__global__ void __launch_bounds__(BT, 3) lbs_kernel(
    const float* __restrict__ points,   // [N,3]
    const float* __restrict__ weights,  // [N,55]
    const float* __restrict__ se3g,     // [55,4,4]
    float* __restrict__ out,            // [N,3]
    int N, int ntiles)
{
    extern __shared__ unsigned char smem_raw[];
    ulonglong2* se3_s = (ulonglong2*)smem_raw;                  // [NJ*3]
    float*      w_all = (float*)(smem_raw + NJ * 3 * 16);       // [WARPS][WSLICE]

    const int tid  = threadIdx.x;
    const int wid  = tid >> 5;
    const int lane = tid & 31;

    // ---- SE3 rows 0..2 -> SMEM once per persistent block ----
    for (int idx = tid; idx < NJ * 3; idx += BT) {
        const int j = idx / 3, k = idx - j * 3;
        se3_s[idx] = *reinterpret_cast<const ulonglong2*>(se3g + j * 16 + k * 4);
    }
    __syncthreads();   // only block-wide sync in the kernel

    float* __restrict__ ws = w_all + wid * WSLICE;
    const int tstride = gridDim.x * WARPS;

    for (int t = blockIdx.x * WARPS + wid; t < ntiles; t += tstride) {
        const int base = t * TV;
        const int nv   = min(TV, N - base);

        const int v0 = base + lane;            // first vertex: lane
        const int v1 = base + lane + 32;       // second vertex: lane+32
        const bool valid0 = (lane      < nv);
        const bool valid1 = (lane + 32 < nv);
        const int pv0 = valid0 ? v0 : base;
        const int pv1 = valid1 ? v1 : base;

        // Points early (independent of staging).
        const float p0x = points[3 * pv0 + 0];
        const float p0y = points[3 * pv0 + 1];
        const float p0z = points[3 * pv0 + 2];
        const float p1x = points[3 * pv1 + 0];
        const float p1y = points[3 * pv1 + 1];
        const float p1z = points[3 * pv1 + 2];

        // ---- stage 64 contiguous weight rows (14080B, coalesced) ----
        if (nv == TV) {
            const float4* __restrict__ src =
                reinterpret_cast<const float4*>(weights + (size_t)base * NJ);
            float4* __restrict__ dst = reinterpret_cast<float4*>(ws);
            float4 r[NCHUNK];
            #pragma unroll
            for (int k = 0; k < NCHUNK; k++) {           // front-batched LDGs
                const int i = lane + k * 32;
                if (i < NQ) r[k] = src[i];
            }
            #pragma unroll
            for (int k = 0; k < NCHUNK; k++) {
                const int i = lane + k * 32;
                if (i < NQ) dst[i] = r[k];
            }
        } else {
            const float* __restrict__ src = weights + (size_t)base * NJ;
            for (int i = lane; i < nv * NJ; i += 32) ws[i] = src[i];
        }
        __syncwarp();

        // ---- compute both vertices; SE3 loads shared ----
        unsigned long long a000 = 0, a001 = 0, a010 = 0, a011 = 0, a020 = 0, a021 = 0;
        unsigned long long a100 = 0, a101 = 0, a110 = 0, a111 = 0, a120 = 0, a121 = 0;
        const float* __restrict__ wp0 = ws + lane * NJ;          // stride 55: cf-free
        const float* __restrict__ wp1 = ws + (lane + 32) * NJ;   // +32*55: cf-free

        #pragma unroll 11
        for (int j = 0; j < NJ; j++) {
            const float w0 = wp0[j];
            const float w1 = wp1[j];
            unsigned long long ww0, ww1;
            PACK_DUP(ww0, w0);
            PACK_DUP(ww1, w1);
            const ulonglong2 r0 = se3_s[j * 3 + 0];      // LDS.128 broadcast
            const ulonglong2 r1 = se3_s[j * 3 + 1];
            const ulonglong2 r2 = se3_s[j * 3 + 2];
            FMA2(a000, ww0, r0.x); FMA2(a001, ww0, r0.y);
            FMA2(a010, ww0, r1.x); FMA2(a011, ww0, r1.y);
            FMA2(a020, ww0, r2.x); FMA2(a021, ww0, r2.y);
            FMA2(a100, ww1, r0.x); FMA2(a101, ww1, r0.y);
            FMA2(a110, ww1, r1.x); FMA2(a111, ww1, r1.y);
            FMA2(a120, ww1, r2.x); FMA2(a121, ww1, r2.y);
        }

        float m0, m1, m2, m3;
        if (valid0) {
            float o0, o1, o2;
            UNPACK2(m0, m1, a000); UNPACK2(m2, m3, a001);
            o0 = fmaf(m0, p0x, fmaf(m1, p0y, fmaf(m2, p0z, m3)));
            UNPACK2(m0, m1, a010); UNPACK2(m2, m3, a011);
            o1 = fmaf(m0, p0x, fmaf(m1, p0y, fmaf(m2, p0z, m3)));
            UNPACK2(m0, m1, a020); UNPACK2(m2, m3, a021);
            o2 = fmaf(m0, p0x, fmaf(m1, p0y, fmaf(m2, p0z, m3)));
            out[3 * v0 + 0] = o0;
            out[3 * v0 + 1] = o1;
            out[3 * v0 + 2] = o2;
        }
        if (valid1) {
            float o0, o1, o2;
            UNPACK2(m0, m1, a100); UNPACK2(m2, m3, a101);
            o0 = fmaf(m0, p1x, fmaf(m1, p1y, fmaf(m2, p1z, m3)));
            UNPACK2(m0, m1, a110); UNPACK2(m2, m3, a111);
            o1 = fmaf(m0, p1x, fmaf(m1, p1y, fmaf(m2, p1z, m3)));
            UNPACK2(m0, m1, a120); UNPACK2(m2, m3, a121);
            o2 = fmaf(m0, p1x, fmaf(m1, p1y, fmaf(m2, p1z, m3)));
            out[3 * v1 + 0] = o0;
            out[3 * v1 + 1] = o1;
            out[3 * v1 + 2] = o2;
        }
        __syncwarp();   // slice fully read before next stage overwrites
    }
}

extern "C" void kernel_launch(void* const* d_in, const int* in_sizes, int n_in,
                              void* d_out, int out_size)
{
    const float* points  = (const float*)d_in[0];  // [N,3]
    const float* weights = (const float*)d_in[1];  // [N,55]
    const float* se3     = (const float*)d_in[2];  // [55,4,4]
    float* out           = (float*)d_out;          // [N,3]

    const int N      = in_sizes[0] / 3;
    const int ntiles = (N + TV - 1) / TV;

    int grid = 148 * 6;                       // persistent: 3 blocks/SM * ~2 waves of tiles
    const int maxg = (ntiles + WARPS - 1) / WARPS;
    if (grid > maxg) grid = maxg;

    static bool attr_set = false;
    if (!attr_set) {
        cudaFuncSetAttribute(lbs_kernel,
                             cudaFuncAttributeMaxDynamicSharedMemorySize,
                             SMEM_BYTES);
        attr_set = true;
    }
    lbs_kernel<<<grid, BT, SMEM_BYTES>>>(points, weights, se3, out, N, ntiles);
}